// round 2
// baseline (speedup 1.0000x reference)
#include <cuda_runtime.h>
#include <cuda_bf16.h>
#include <mma.h>

using namespace nvcuda;

// Problem constants
#define NTOK   8192
#define INDIM  4096
#define OUTDIM 4096
#define NE     8
#define RR     16
#define H4E    32
#define CAPACITY 3072          // int(3.0 * 8192 / 8)
#define ALPHA_ (1.0f/16.0f)
#define LN_EPS 1e-5f

// Scratch (no allocation allowed -> device globals)
__device__ float g_C2[NTOK * 128];      // augmented-A columns [N, E*R]
__device__ int   g_topi[NTOK * 2];
__device__ float g_topg[NTOK * 2];
__device__ int   g_counts[16];          // [k][e]

// ---------------------------------------------------------------------------
// cp.async helpers
// ---------------------------------------------------------------------------
__device__ __forceinline__ unsigned smem_u32(const void* p) {
    return (unsigned)__cvta_generic_to_shared(p);
}
__device__ __forceinline__ void cp16(void* dst, const void* src) {
    asm volatile("cp.async.cg.shared.global [%0], [%1], 16;\n"
                 :: "r"(smem_u32(dst)), "l"(src));
}
__device__ __forceinline__ void cp4(void* dst, const void* src) {
    asm volatile("cp.async.ca.shared.global [%0], [%1], 4;\n"
                 :: "r"(smem_u32(dst)), "l"(src));
}
__device__ __forceinline__ void cp_commit() {
    asm volatile("cp.async.commit_group;\n");
}
#define CP_WAIT(n) asm volatile("cp.async.wait_group %0;\n" :: "n"(n))

// ---------------------------------------------------------------------------
// Kernel 0: zero the routing counters
// ---------------------------------------------------------------------------
__global__ void zero_counts_kernel() {
    if (threadIdx.x < 16) g_counts[threadIdx.x] = 0;
}

// ---------------------------------------------------------------------------
// Kernel 1: gate = Linear(4096->32) -> LayerNorm -> ReLU -> Linear(32->8)
//           -> top-2 -> softmax over selected -> counts
// One block of 256 threads handles 64 tokens.
// ---------------------------------------------------------------------------
__global__ __launch_bounds__(256) void gate_kernel(
    const float* __restrict__ x,
    const float* __restrict__ gw1, const float* __restrict__ gb1,
    const float* __restrict__ gamma, const float* __restrict__ beta,
    const float* __restrict__ gw2, const float* __restrict__ gb2)
{
    __shared__ float Xs[64][65];   // [k][m]
    __shared__ float Wsh[64][33];  // [k][j]
    __shared__ float Hs[64][33];   // [m][j]

    const int tid = threadIdx.x;
    const int m0  = blockIdx.x * 64;
    const int mm  = tid & 63;
    const int jg  = tid >> 6;      // 0..3
    const int j0  = jg * 8;

    float acc[8];
#pragma unroll
    for (int jj = 0; jj < 8; jj++) acc[jj] = 0.f;

    for (int kc = 0; kc < 64; ++kc) {
        const int k0 = kc * 64;
        // load x chunk [64 tokens][64 k], store transposed [k][m]
#pragma unroll
        for (int i = 0; i < 4; i++) {
            int s  = tid + i * 256;        // 0..1023 float4 slots
            int m  = s >> 4;
            int f4 = (s & 15) * 4;
            float4 v = *(const float4*)(x + (size_t)(m0 + m) * INDIM + k0 + f4);
            Xs[f4 + 0][m] = v.x; Xs[f4 + 1][m] = v.y;
            Xs[f4 + 2][m] = v.z; Xs[f4 + 3][m] = v.w;
        }
        // load gw1 chunk [32 j][64 k], store transposed [k][j]
#pragma unroll
        for (int i = 0; i < 2; i++) {
            int s  = tid + i * 256;        // 0..511
            int j  = s >> 4;
            int f4 = (s & 15) * 4;
            float4 v = *(const float4*)(gw1 + (size_t)j * INDIM + k0 + f4);
            Wsh[f4 + 0][j] = v.x; Wsh[f4 + 1][j] = v.y;
            Wsh[f4 + 2][j] = v.z; Wsh[f4 + 3][j] = v.w;
        }
        __syncthreads();
#pragma unroll 16
        for (int kk = 0; kk < 64; ++kk) {
            float xv = Xs[kk][mm];
#pragma unroll
            for (int jj = 0; jj < 8; jj++) acc[jj] += xv * Wsh[kk][j0 + jj];
        }
        __syncthreads();
    }

#pragma unroll
    for (int jj = 0; jj < 8; jj++) Hs[mm][j0 + jj] = acc[jj];
    __syncthreads();

    if (tid < 64) {
        const int n = m0 + tid;
        float h[H4E];
        float mu = 0.f;
#pragma unroll
        for (int j = 0; j < H4E; j++) { h[j] = Hs[tid][j] + gb1[j]; mu += h[j]; }
        mu *= (1.0f / H4E);
        float var = 0.f;
#pragma unroll
        for (int j = 0; j < H4E; j++) { float d = h[j] - mu; var += d * d; }
        var *= (1.0f / H4E);
        const float inv = rsqrtf(var + LN_EPS);
#pragma unroll
        for (int j = 0; j < H4E; j++) {
            float v = (h[j] - mu) * inv * gamma[j] + beta[j];
            h[j] = fmaxf(v, 0.f);
        }
        // gates + top-2 (first-occurrence semantics, matching lax.top_k ties)
        float best = -3.4e38f, second = -3.4e38f;
        int be = 0, se = 0;
#pragma unroll
        for (int e = 0; e < NE; e++) {
            float g = gb2[e];
#pragma unroll
            for (int j = 0; j < H4E; j++) g += h[j] * gw2[e * H4E + j];
            if (g > best)      { second = best; se = be; best = g; be = e; }
            else if (g > second) { second = g; se = e; }
        }
        const float e1 = __expf(second - best);
        const float s  = 1.f + e1;
        g_topi[n * 2 + 0] = be;
        g_topi[n * 2 + 1] = se;
        g_topg[n * 2 + 0] = 1.f / s;
        g_topg[n * 2 + 1] = e1 / s;
        atomicAdd(&g_counts[be], 1);
        atomicAdd(&g_counts[8 + se], 1);
    }
}

// ---------------------------------------------------------------------------
// Kernel 2: C2[n, e*16+r] = w[n,e] * ALPHA * dot(x[n], lora_A[e][:, r])
// One block (128 threads) per token. r4 = (tid&3)*4 (4 r's per thread),
// p = tid>>2 (32 K-stripes of 128).
// ---------------------------------------------------------------------------
__global__ __launch_bounds__(128) void coeff_kernel(
    const float* __restrict__ x, const float* __restrict__ lA)
{
    const int n   = blockIdx.x;
    const int tid = threadIdx.x;

    g_C2[(size_t)n * 128 + tid] = 0.f;   // zero full row first

    const int   e0 = g_topi[n * 2 + 0];
    const int   e1 = g_topi[n * 2 + 1];
    const float w0 = g_topg[n * 2 + 0] * (g_counts[e0]     <= CAPACITY ? 1.f : 0.f);
    const float w1 = g_topg[n * 2 + 1] * (g_counts[8 + e1] <= CAPACITY ? 1.f : 0.f);

    const int r4 = (tid & 3) << 2;
    const int p  = tid >> 2;
    const int i0 = p * 128;

    const float* xr  = x  + (size_t)n  * INDIM;
    const float* A0b = lA + (size_t)e0 * INDIM * RR;
    const float* A1b = lA + (size_t)e1 * INDIM * RR;

    float acc0[4] = {0.f, 0.f, 0.f, 0.f};
    float acc1[4] = {0.f, 0.f, 0.f, 0.f};

    for (int ii = 0; ii < 128; ii += 4) {
        float4 xv = *(const float4*)(xr + i0 + ii);
        float xs[4] = {xv.x, xv.y, xv.z, xv.w};
#pragma unroll
        for (int q = 0; q < 4; q++) {
            const int i = i0 + ii + q;
            float4 a0 = *(const float4*)(A0b + (size_t)i * RR + r4);
            float4 a1 = *(const float4*)(A1b + (size_t)i * RR + r4);
            acc0[0] += xs[q] * a0.x; acc0[1] += xs[q] * a0.y;
            acc0[2] += xs[q] * a0.z; acc0[3] += xs[q] * a0.w;
            acc1[0] += xs[q] * a1.x; acc1[1] += xs[q] * a1.y;
            acc1[2] += xs[q] * a1.z; acc1[3] += xs[q] * a1.w;
        }
    }

    __shared__ float sh[2][32 * 16];
#pragma unroll
    for (int j = 0; j < 4; j++) {
        sh[0][p * 16 + r4 + j] = acc0[j];
        sh[1][p * 16 + r4 + j] = acc1[j];
    }
    __syncthreads();
    for (int off = 16; off >= 1; off >>= 1) {
        for (int s2 = tid; s2 < off * 16; s2 += 128) {
            const int pp = s2 >> 4, r = s2 & 15;
            sh[0][pp * 16 + r] += sh[0][(pp + off) * 16 + r];
            sh[1][pp * 16 + r] += sh[1][(pp + off) * 16 + r];
        }
        __syncthreads();
    }
    if (tid < 16) {
        g_C2[(size_t)n * 128 + e0 * 16 + tid] = w0 * ALPHA_ * sh[0][tid];
        g_C2[(size_t)n * 128 + e1 * 16 + tid] = w1 * ALPHA_ * sh[1][tid];
    }
}

// ---------------------------------------------------------------------------
// Kernel 3: augmented-K TF32 GEMM.
// out[n,o] = sum_{k<4096} x[n,k] W[o,k]  +  sum_{j<128} C2[n,j] loraB_flat[j,o]
// BM=BN=128, BK=16, 256 threads (8 warps: 4 in M x 2 in N), warp tile 32x64,
// wmma m16n16k8 TF32, 2-stage cp.async double buffering.
// ---------------------------------------------------------------------------
#define BM 128
#define BN 128
#define BK 16
#define ALD 24
#define BLD 24
#define ASZ (BM * ALD)
#define BSZ (BN * BLD)
#define KTILES 264   // (4096 + 128) / 16

__global__ __launch_bounds__(256) void main_gemm_kernel(
    const float* __restrict__ x, const float* __restrict__ W,
    const float* __restrict__ LB, float* __restrict__ out)
{
    extern __shared__ float smem[];
    float* Asm = smem;              // [2][ASZ]
    float* Bsm = smem + 2 * ASZ;    // [2][BSZ]

    const int tid = threadIdx.x;
    const int gm0 = blockIdx.y * BM;
    const int gn0 = blockIdx.x * BN;
    const int warp = tid >> 5;
    const int wm = warp & 3;        // 0..3 -> M offset wm*32
    const int wn = warp >> 2;       // 0..1 -> N offset wn*64

    wmma::fragment<wmma::accumulator, 16, 16, 8, float> cf[2][4];
#pragma unroll
    for (int i = 0; i < 2; i++)
#pragma unroll
        for (int j = 0; j < 4; j++) wmma::fill_fragment(cf[i][j], 0.f);

    auto load_tile = [&](int kt, int buf) {
        float* Ad = Asm + buf * ASZ;
        float* Bd = Bsm + buf * BSZ;
        const int k0 = kt * BK;
        // ---- A tile ----
        const float* Abase;
        int Ald_;
        if (k0 < INDIM) { Abase = x + (size_t)gm0 * INDIM + k0;         Ald_ = INDIM; }
        else            { Abase = g_C2 + (size_t)gm0 * 128 + (k0 - INDIM); Ald_ = 128; }
#pragma unroll
        for (int i = 0; i < 2; i++) {
            int s  = tid + i * 256;       // 0..511 float4 slots
            int m  = s >> 2;
            int f4 = (s & 3) << 2;
            cp16(Ad + m * ALD + f4, Abase + (size_t)m * Ald_ + f4);
        }
        // ---- B tile (col-major [n][k]) ----
        if (k0 < INDIM) {
            const float* Bbase = W + (size_t)gn0 * INDIM + k0;
#pragma unroll
            for (int i = 0; i < 2; i++) {
                int s  = tid + i * 256;
                int nn = s >> 2;
                int f4 = (s & 3) << 2;
                cp16(Bd + nn * BLD + f4, Bbase + (size_t)nn * INDIM + f4);
            }
        } else {
            // loraB_flat[j, o] is row-major in o -> scalar cp.async, coalesced in o
            const float* Lbase = LB + (size_t)(k0 - INDIM) * OUTDIM + gn0;
#pragma unroll
            for (int i = 0; i < 8; i++) {
                int s  = tid + (i << 8);   // 0..2047
                int k  = s >> 7;
                int nn = s & 127;
                cp4(Bd + nn * BLD + k, Lbase + (size_t)k * OUTDIM + nn);
            }
        }
        cp_commit();
    };

    load_tile(0, 0);
    for (int kt = 0; kt < KTILES; ++kt) {
        const int buf = kt & 1;
        if (kt + 1 < KTILES) { load_tile(kt + 1, buf ^ 1); CP_WAIT(1); }
        else                 { CP_WAIT(0); }
        __syncthreads();

        const float* Ad = Asm + buf * ASZ;
        const float* Bd = Bsm + buf * BSZ;
#pragma unroll
        for (int kk = 0; kk < BK; kk += 8) {
            wmma::fragment<wmma::matrix_a, 16, 16, 8, wmma::precision::tf32, wmma::row_major> af[2];
            wmma::fragment<wmma::matrix_b, 16, 16, 8, wmma::precision::tf32, wmma::col_major> bf[4];
#pragma unroll
            for (int i = 0; i < 2; i++) {
                wmma::load_matrix_sync(af[i], Ad + (wm * 32 + i * 16) * ALD + kk, ALD);
#pragma unroll
                for (int t = 0; t < af[i].num_elements; t++)
                    af[i].x[t] = wmma::__float_to_tf32(af[i].x[t]);
            }
#pragma unroll
            for (int j = 0; j < 4; j++) {
                wmma::load_matrix_sync(bf[j], Bd + (wn * 64 + j * 16) * BLD + kk, BLD);
#pragma unroll
                for (int t = 0; t < bf[j].num_elements; t++)
                    bf[j].x[t] = wmma::__float_to_tf32(bf[j].x[t]);
            }
#pragma unroll
            for (int i = 0; i < 2; i++)
#pragma unroll
                for (int j = 0; j < 4; j++)
                    wmma::mma_sync(cf[i][j], af[i], bf[j], cf[i][j]);
        }
        __syncthreads();
    }

#pragma unroll
    for (int i = 0; i < 2; i++)
#pragma unroll
        for (int j = 0; j < 4; j++)
            wmma::store_matrix_sync(
                out + (size_t)(gm0 + wm * 32 + i * 16) * OUTDIM + gn0 + wn * 64 + j * 16,
                cf[i][j], OUTDIM, wmma::mem_row_major);
}

// ---------------------------------------------------------------------------
// Host entry
// ---------------------------------------------------------------------------
extern "C" void kernel_launch(void* const* d_in, const int* in_sizes, int n_in,
                              void* d_out, int out_size)
{
    const float* x    = (const float*)d_in[0];
    const float* W    = (const float*)d_in[1];
    const float* lA   = (const float*)d_in[2];
    const float* lB   = (const float*)d_in[3];
    const float* gw1  = (const float*)d_in[4];
    const float* gb1  = (const float*)d_in[5];
    const float* gam  = (const float*)d_in[6];
    const float* bet  = (const float*)d_in[7];
    const float* gw2  = (const float*)d_in[8];
    const float* gb2  = (const float*)d_in[9];
    float* out = (float*)d_out;

    zero_counts_kernel<<<1, 32>>>();
    gate_kernel<<<NTOK / 64, 256>>>(x, gw1, gb1, gam, bet, gw2, gb2);
    coeff_kernel<<<NTOK, 128>>>(x, lA);

    const size_t smem_bytes = 2 * (ASZ + BSZ) * sizeof(float);  // 49152
    main_gemm_kernel<<<dim3(OUTDIM / BN, NTOK / BM), 256, smem_bytes>>>(x, W, lB, out);
}